// round 5
// baseline (speedup 1.0000x reference)
#include <cuda_runtime.h>
#include <cuda_fp16.h>
#include <math_constants.h>
#include <cstdint>

// GaussianMixture N=131072, K=256, D=32 via mma.sync (sm_103 baseline).
// q_ik = x~^T Atil_k x~ over 561 packed pairs (pad 576).
// Round 5: centered 2-split GEMM. C'_k = C_k - Cbar; D = (Vh+Vl)*fp16(C');
// q = s_i + D with s_i = x~^T Abar x~ exact fp32 per point (k-independent,
// folded into LSE as a shift). Tensor work is 2/3 of round 4.

#define N_PTS   131072
#define K_CL    256
#define SEC     576
#define NPC     9
#define M_CTA   128
#define TPB     256

typedef unsigned long long u64;

__device__ __align__(128) __half g_B2[NPC * 16384];   // centered Ch, swizzled
__device__ float g_Cf[K_CL * SEC];                    // fp32 coefs
__device__ float g_Cbar[SEC];                         // mean coefs
__device__ int   g_kmap[SEC];
__device__ float g_logcoef[K_CL];

// ---------------- helpers ----------------
__device__ __forceinline__ uint32_t smem_u32(const void* p) {
    uint32_t a;
    asm("{ .reg .u64 t; cvta.to.shared.u64 t, %1; cvt.u32.u64 %0, t; }"
        : "=r"(a) : "l"(p));
    return a;
}
__device__ __forceinline__ void ldsm_x4(uint32_t r[4], uint32_t addr) {
    asm volatile("ldmatrix.sync.aligned.m8n8.x4.shared.b16 {%0,%1,%2,%3}, [%4];"
        : "=r"(r[0]), "=r"(r[1]), "=r"(r[2]), "=r"(r[3]) : "r"(addr));
}

#define MBARRIER_INIT(a, n) \
    asm volatile("mbarrier.init.shared.b64 [%0], %1;" \
                 :: "r"((uint32_t)(a)), "r"((uint32_t)(n)) : "memory")
#define MBARRIER_EXPECT_TX(a, b) \
    asm volatile("mbarrier.arrive.expect_tx.shared.b64 _, [%0], %1;" \
                 :: "r"((uint32_t)(a)), "r"((uint32_t)(b)) : "memory")
#define MBARRIER_WAIT_PARITY(mbar, parity) do {                                   \
    uint32_t _m = (uint32_t)(mbar); uint32_t _p = (uint32_t)(parity);             \
    uint32_t _done;                                                               \
    asm volatile("{\n\t.reg .pred p;\n\t"                                         \
        "mbarrier.try_wait.parity.acquire.cta.shared::cta.b64 p, [%1], %2;\n\t"   \
        "selp.b32 %0, 1, 0, p;\n\t}" : "=r"(_done) : "r"(_m), "r"(_p) : "memory");\
    if (!_done) {                                                                 \
        asm volatile("{\n\t.reg .pred P1;\n\t"                                    \
        "WAIT_LOOP_%=:\n\t"                                                       \
        "mbarrier.try_wait.parity.acquire.cta.shared::cta.b64 P1, [%0], %1, 0x989680;\n\t" \
        "@P1 bra.uni WAIT_DONE_%=;\n\t"                                           \
        "bra.uni WAIT_LOOP_%=;\n\t"                                               \
        "WAIT_DONE_%=:\n\t}" :: "r"(_m), "r"(_p) : "memory");                     \
    }                                                                             \
} while (0)

__device__ __forceinline__ void bulk_g2s(uint32_t dst, const void* src,
                                         uint32_t bytes, uint32_t mbar) {
    asm volatile(
        "cp.async.bulk.shared::cluster.global.mbarrier::complete_tx::bytes "
        "[%0], [%1], %2, [%3];"
        :: "r"(dst), "l"(src), "r"(bytes), "r"(mbar) : "memory");
}

__device__ __forceinline__ void unrank_pair(int p, int& d, int& f) {
    int dd = 0;
    while (true) {
        int len = 33 - dd;
        if (p < len) { d = dd; f = dd + p; return; }
        p -= len; ++dd;
    }
}

// ============================================================================
// Prep 1 (one block per cluster): fp32 coefs, logcoef, kmap
// ============================================================================
__global__ void __launch_bounds__(128) prep_kernel(
    const float* __restrict__ centers,
    const float* __restrict__ S_all,
    const float* __restrict__ weights)
{
    __shared__ float sS[32][33];
    __shared__ float sA[32][33];
    __shared__ float sCen[32];
    __shared__ float sM[32];
    __shared__ float sLogSumW, sCAC;

    const int k = blockIdx.x;
    const int tid = threadIdx.x;
    const float* Sg = S_all + (size_t)k * 1024;

    for (int i = tid; i < 1024; i += 128) sS[i >> 5][i & 31] = Sg[i];
    if (tid < 32) sCen[tid] = centers[k * 32 + tid];
    __syncthreads();

    if (tid < 32) {
        float s = 0.f;
        for (int j = tid; j < K_CL; j += 32) s += fabsf(weights[j]);
        #pragma unroll
        for (int o = 16; o; o >>= 1) s += __shfl_xor_sync(0xffffffffu, s, o);
        if (tid == 0) sLogSumW = logf(s + 1e-30f);
    }

    for (int i = tid; i < 1024; i += 128) {
        int d = i >> 5, f = i & 31;
        float acc = 0.f;
        #pragma unroll
        for (int e = 0; e < 32; ++e) acc += sS[d][e] * sS[f][e];
        sA[d][f] = acc;
    }
    __syncthreads();

    if (tid < 32) {
        float md = 0.f;
        #pragma unroll
        for (int f = 0; f < 32; ++f) md += sA[tid][f] * sCen[f];
        sM[tid] = md;
        float t = md * sCen[tid];
        #pragma unroll
        for (int o = 16; o; o >>= 1) t += __shfl_xor_sync(0xffffffffu, t, o);
        if (tid == 0) sCAC = t;
    }
    __syncthreads();

    // fp32 coefs (pads = 0)
    for (int p = tid; p < SEC; p += 128) {
        float coef = 0.f;
        if (p < 561) {
            int d, f; unrank_pair(p, d, f);
            if (f < 32)      coef = (d == f) ? sA[d][d] : 2.f * sA[d][f];
            else if (d < 32) coef = -2.f * sM[d];
            else             coef = sCAC;
        }
        g_Cf[k * SEC + p] = coef;
    }
    __syncthreads();

    if (tid < 32) {
        const int i = tid;
        for (int j = 0; j < 32; ++j) {
            float diag = sqrtf(sA[j][j]);
            __syncwarp();
            if (i == j) sA[j][j] = diag;
            else if (i > j) sA[i][j] = sA[i][j] / diag;
            __syncwarp();
            float lij = (i > j) ? sA[i][j] : 0.f;
            for (int c = j + 1; c <= i; ++c) sA[i][c] -= lij * sA[c][j];
            __syncwarp();
        }
        float ld = logf(sA[i][i]);
        #pragma unroll
        for (int o = 16; o; o >>= 1) ld += __shfl_xor_sync(0xffffffffu, ld, o);
        if (tid == 0)
            g_logcoef[k] = logf(fabsf(weights[k])) - sLogSumW + ld;
    }

    if (blockIdx.x == 0) {
        for (int p = tid; p < SEC; p += 128) {
            int d = 0, f = 0;
            if (p < 561) unrank_pair(p, d, f);
            g_kmap[p] = d | (f << 8);
        }
    }
}

// ============================================================================
// Prep 2 (block per chunk, thread per cluster): Cbar + centered fp16 B image
// ============================================================================
__global__ void __launch_bounds__(256) bprep_kernel()
{
    __shared__ float red[8];
    __shared__ float mean;

    const int pc = blockIdx.x;
    const int k = threadIdx.x;
    const int wid = k >> 5, lane = k & 31;

    for (int kl = 0; kl < 64; ++kl) {
        const int p = pc * 64 + kl;
        const float c = g_Cf[k * SEC + p];
        float s = c;
        #pragma unroll
        for (int o = 16; o; o >>= 1) s += __shfl_xor_sync(0xffffffffu, s, o);
        if (lane == 0) red[wid] = s;
        __syncthreads();
        if (k == 0) {
            float t = 0.f;
            #pragma unroll
            for (int w = 0; w < 8; ++w) t += red[w];
            const float m = t * (1.f / 256.f);
            mean = m;
            g_Cbar[p] = m;
        }
        __syncthreads();
        const __half ch = __float2half_rn(c - mean);
        const uint32_t raw = (uint32_t)(k * 128 + kl * 2);
        const uint32_t swz = raw ^ ((raw >> 3) & 0x70);
        *(__half*)((char*)g_B2 + (size_t)pc * 32768 + swz) = ch;
    }
}

// ============================================================================
// Main kernel
// ============================================================================
#define OFF_A    0u         // 2 buf x [hi 16K | lo 16K] = 65536
#define OFF_B    65536u     // 2 buf x 32K = 65536
#define OFF_X    131072u    // 128*33*4 = 16896
#define OFF_KM   147968u    // 576*4
#define OFF_LOG  150272u    // 256*4
#define OFF_CBAR 151296u    // 576*4
#define OFF_S    153600u    // 256*4
#define OFF_RED  154624u    // 128*4 float2
#define OFF_BAR  158720u
#define SMEM_END 158736u
#define SMEM_BYTES (SMEM_END + 1024u)

__device__ __forceinline__ void build_a_tiles(
    const float* __restrict__ px, const int* __restrict__ sKm,
    int pc, int h, char* aHi, char* aLo, int p)
{
    const int pbase = pc * 64 + h * 32;
    const int rowbyte = p * 128;
    const int msk = (p & 7) << 4;
    #pragma unroll
    for (int g = 0; g < 4; ++g) {
        uint32_t wh[4], wl[4];
        #pragma unroll
        for (int q = 0; q < 4; ++q) {
            unsigned short hs[2], ls[2];
            #pragma unroll
            for (int e = 0; e < 2; ++e) {
                const int mp = sKm[pbase + g * 8 + q * 2 + e];
                const float v = px[mp & 255] * px[mp >> 8];
                const __half hi = __float2half_rn(v);
                const __half lo = __float2half_rn(v - __half2float(hi));
                hs[e] = __half_as_ushort(hi);
                ls[e] = __half_as_ushort(lo);
            }
            wh[q] = (uint32_t)hs[0] | ((uint32_t)hs[1] << 16);
            wl[q] = (uint32_t)ls[0] | ((uint32_t)ls[1] << 16);
        }
        const int off = rowbyte + ((h * 64 + g * 16) ^ msk);
        *(uint4*)(aHi + off) = make_uint4(wh[0], wh[1], wh[2], wh[3]);
        *(uint4*)(aLo + off) = make_uint4(wl[0], wl[1], wl[2], wl[3]);
    }
}

__device__ __forceinline__ void hmma_all(
    float (&acc)[4][8][4], const uint32_t (&a)[4][4], const uint32_t (&b)[4][4])
{
    #pragma unroll
    for (int mt = 0; mt < 4; ++mt)
        #pragma unroll
        for (int j = 0; j < 8; ++j) {
            const uint32_t b0 = b[j >> 1][(j & 1) * 2];
            const uint32_t b1 = b[j >> 1][(j & 1) * 2 + 1];
            asm volatile(
                "mma.sync.aligned.m16n8k16.row.col.f32.f16.f16.f32 "
                "{%0,%1,%2,%3}, {%4,%5,%6,%7}, {%8,%9}, {%0,%1,%2,%3};"
                : "+f"(acc[mt][j][0]), "+f"(acc[mt][j][1]),
                  "+f"(acc[mt][j][2]), "+f"(acc[mt][j][3])
                : "r"(a[mt][0]), "r"(a[mt][1]), "r"(a[mt][2]), "r"(a[mt][3]),
                  "r"(b0), "r"(b1));
        }
}

// 2-split chunk: per ks load aHi/b/aLo once, two HMMA passes.
__device__ __forceinline__ void mma_chunk(
    uint32_t aHiT, uint32_t bT, float (&acc)[4][8][4],
    int lane, int warpM, int warpN)
{
    const uint32_t aLoT = aHiT + 16384u;

    const int rowA = (lane & 7) + ((lane >> 3) & 1) * 8;
    const int khA  = (lane >> 4) & 1;
    const int rowB = (lane & 7) + ((lane >> 4) & 1) * 8;
    const int khB  = (lane >> 3) & 1;
    const int sm   = (lane & 7) << 4;

    uint32_t aBase[4], bBase[4];
    #pragma unroll
    for (int mt = 0; mt < 4; ++mt)
        aBase[mt] = (uint32_t)((warpM * 64 + mt * 16 + rowA) * 128);
    #pragma unroll
    for (int nt = 0; nt < 4; ++nt)
        bBase[nt] = (uint32_t)((warpN * 64 + nt * 16 + rowB) * 128);

    #pragma unroll
    for (int ks = 0; ks < 4; ++ks) {
        const uint32_t colA = (uint32_t)((ks * 32 + khA * 16) ^ sm);
        const uint32_t colB = (uint32_t)((ks * 32 + khB * 16) ^ sm);

        uint32_t aH[4][4], aL[4][4], bb[4][4];
        #pragma unroll
        for (int mt = 0; mt < 4; ++mt) ldsm_x4(aH[mt], aHiT + aBase[mt] + colA);
        #pragma unroll
        for (int nt = 0; nt < 4; ++nt) ldsm_x4(bb[nt], bT + bBase[nt] + colB);
        hmma_all(acc, aH, bb);                       // Vh * C'
        #pragma unroll
        for (int mt = 0; mt < 4; ++mt) ldsm_x4(aL[mt], aLoT + aBase[mt] + colA);
        hmma_all(acc, aL, bb);                       // Vl * C'
    }
}

__global__ void __launch_bounds__(TPB, 1)
gmm_mma_kernel(const float* __restrict__ points,
               const float* __restrict__ threshold,
               float* __restrict__ out)
{
    extern __shared__ char dsm[];
    const uint32_t rawb = smem_u32(dsm);
    const uint32_t base = (rawb + 1023u) & ~1023u;
    char* bp = dsm + (base - rawb);

    float* sX    = (float*)(bp + OFF_X);
    int*   sKm   = (int*)(bp + OFF_KM);
    float* sLog  = (float*)(bp + OFF_LOG);
    float* sCbar = (float*)(bp + OFF_CBAR);
    float* sS    = (float*)(bp + OFF_S);
    float2* sRed = (float2*)(bp + OFF_RED);

    const int tid = threadIdx.x;
    const int wid = tid >> 5;
    const int lane = tid & 31;
    const int gid = lane >> 2;
    const int tig = lane & 3;
    const int warpM = wid >> 2;
    const int warpN = wid & 3;
    const int p = tid & 127;
    const int h = tid >> 7;

    for (int i = tid; i < SEC; i += TPB) sKm[i] = g_kmap[i];
    for (int i = tid; i < SEC; i += TPB) sCbar[i] = g_Cbar[i];
    if (tid < K_CL) sLog[tid] = g_logcoef[tid];
    {
        const float4* src = (const float4*)(points +
            ((size_t)blockIdx.x * M_CTA + p) * 32 + h * 16);
        float* xr = sX + p * 33;
        #pragma unroll
        for (int r = 0; r < 4; ++r) {
            float4 v = src[r];
            xr[h * 16 + 4 * r] = v.x; xr[h * 16 + 4 * r + 1] = v.y;
            xr[h * 16 + 4 * r + 2] = v.z; xr[h * 16 + 4 * r + 3] = v.w;
        }
        if (h == 0) xr[32] = 1.0f;
    }

    const uint32_t bar[2] = { base + OFF_BAR, base + OFF_BAR + 8u };
    if (tid == 0) { MBARRIER_INIT(bar[0], 1); MBARRIER_INIT(bar[1], 1); }
    __syncthreads();

    const float* px = sX + p * 33;
    float acc[4][8][4];
    #pragma unroll
    for (int m = 0; m < 4; ++m)
        #pragma unroll
        for (int n = 0; n < 8; ++n)
            #pragma unroll
            for (int e = 0; e < 4; ++e) acc[m][n][e] = 0.f;

    // prologue: B chunk 0, A chunk 0, then s_i (overlaps B0 flight)
    if (tid == 0) {
        MBARRIER_EXPECT_TX(bar[0], 32768u);
        bulk_g2s(base + OFF_B, (const char*)g_B2, 32768u, bar[0]);
    }
    build_a_tiles(px, sKm, 0, h, bp + OFF_A, bp + OFF_A + 16384u, p);

    // s_i = x~^T Abar x~ (exact fp32); this thread's half of the pairs
    {
        float part = 0.f;
        #pragma unroll 8
        for (int t = 0; t < 288; ++t) {
            const int pp = h * 288 + t;
            const int mp = sKm[pp];
            part = fmaf(sCbar[pp], px[mp & 255] * px[mp >> 8], part);
        }
        sS[tid] = part;
    }

    int phv[2] = { 0, 0 };
    for (int pc = 0; pc < NPC; ++pc) {
        const int buf = pc & 1, nb = buf ^ 1;
        MBARRIER_WAIT_PARITY(bar[buf], phv[buf]);
        phv[buf] ^= 1;
        __syncthreads();

        if (pc + 1 < NPC && tid == 0) {
            MBARRIER_EXPECT_TX(bar[nb], 32768u);
            bulk_g2s(base + OFF_B + (uint32_t)nb * 32768u,
                     (const char*)g_B2 + (size_t)(pc + 1) * 32768u,
                     32768u, bar[nb]);
        }

        mma_chunk(base + OFF_A + (uint32_t)buf * 32768u,
                  base + OFF_B + (uint32_t)buf * 32768u,
                  acc, lane, warpM, warpN);

        if (pc + 1 < NPC)
            build_a_tiles(px, sKm, pc + 1, h,
                          bp + OFF_A + (uint32_t)nb * 32768u,
                          bp + OFF_A + (uint32_t)nb * 32768u + 16384u, p);
    }

    // ---- epilogue: weighted logsumexp (shift by -0.5 s_i at the end) ----
    float lc[8][2];
    #pragma unroll
    for (int n = 0; n < 8; ++n) {
        lc[n][0] = sLog[warpN * 64 + n * 8 + tig * 2];
        lc[n][1] = sLog[warpN * 64 + n * 8 + tig * 2 + 1];
    }

    #pragma unroll
    for (int m = 0; m < 4; ++m) {
        #pragma unroll
        for (int rr = 0; rr < 2; ++rr) {
            float mx = -CUDART_INF_F, ss = 0.f;
            #pragma unroll
            for (int n = 0; n < 8; ++n) {
                #pragma unroll
                for (int e = 0; e < 2; ++e) {
                    const float v = fmaf(-0.5f, acc[m][n][rr * 2 + e], lc[n][e]);
                    const float nm = fmaxf(mx, v);
                    ss = ss * __expf(mx - nm) + __expf(v - nm);
                    mx = nm;
                }
            }
            #pragma unroll
            for (int off = 1; off <= 2; off <<= 1) {
                const float om = __shfl_xor_sync(0xffffffffu, mx, off);
                const float os = __shfl_xor_sync(0xffffffffu, ss, off);
                const float nm = fmaxf(mx, om);
                ss = ss * __expf(mx - nm) + os * __expf(om - nm);
                mx = nm;
            }
            if (tig == 0) {
                const int row = warpM * 64 + m * 16 + rr * 8 + gid;
                sRed[row * 4 + warpN] = make_float2(mx, ss);
            }
        }
    }
    __syncthreads();

    if (tid < M_CTA) {
        float2 v = sRed[tid * 4];
        float mx = v.x, ss = v.y;
        #pragma unroll
        for (int w = 1; w < 4; ++w) {
            const float2 o = sRed[tid * 4 + w];
            const float nm = fmaxf(mx, o.x);
            ss = ss * __expf(mx - nm) + o.y * __expf(o.x - nm);
            mx = nm;
        }
        const float s_i = sS[tid] + sS[tid + 128];
        out[(size_t)blockIdx.x * M_CTA + tid] =
            mx + logf(ss) - 0.5f * s_i - threshold[0];
    }
}

extern "C" void kernel_launch(void* const* d_in, const int* in_sizes, int n_in,
                              void* d_out, int out_size)
{
    const float* points  = (const float*)d_in[0];
    const float* centers = (const float*)d_in[1];
    const float* covs    = (const float*)d_in[2];
    const float* weights = (const float*)d_in[3];
    const float* thresh  = (const float*)d_in[4];
    float* out = (float*)d_out;

    cudaFuncSetAttribute(gmm_mma_kernel,
                         cudaFuncAttributeMaxDynamicSharedMemorySize, SMEM_BYTES);

    prep_kernel<<<K_CL, 128>>>(centers, covs, weights);
    bprep_kernel<<<NPC, 256>>>();
    gmm_mma_kernel<<<N_PTS / M_CTA, TPB, SMEM_BYTES>>>(points, thresh, out);
}

// round 6
// speedup vs baseline: 1.4970x; 1.4970x over previous
#include <cuda_runtime.h>
#include <cuda_fp16.h>
#include <math_constants.h>
#include <cstdint>

// GaussianMixture N=131072, K=256, D=32 via mma.sync (sm_103 baseline).
// q_ik = x~^T Atil_k x~ over 561 packed pairs (pad 576).
// Round 6: single-pass centered GEMM. C'_k = C_k - C_0 (cluster-0 centering,
// no cross-cluster reduction); D = fp16(V) * fp16(C'); q = s_i + D with
// s_i = x~^T A_0 x~ exact fp32 per point. Zero-mean-over-k fp16 errors are
// averaged out by the weighted logsumexp (measured effect in rounds 4/5).

#define N_PTS   131072
#define K_CL    256
#define SEC     576
#define NPC     9
#define M_CTA   128
#define TPB     256

typedef unsigned long long u64;

__device__ __align__(128) __half g_B2[NPC * 16384];   // centered fp16 C', swizzled
__device__ float g_Cbar[SEC];                         // cluster-0 fp32 coefs
__device__ int   g_kmap[SEC];
__device__ float g_logcoef[K_CL];

// ---------------- helpers ----------------
__device__ __forceinline__ uint32_t smem_u32(const void* p) {
    uint32_t a;
    asm("{ .reg .u64 t; cvta.to.shared.u64 t, %1; cvt.u32.u64 %0, t; }"
        : "=r"(a) : "l"(p));
    return a;
}
__device__ __forceinline__ void ldsm_x4(uint32_t r[4], uint32_t addr) {
    asm volatile("ldmatrix.sync.aligned.m8n8.x4.shared.b16 {%0,%1,%2,%3}, [%4];"
        : "=r"(r[0]), "=r"(r[1]), "=r"(r[2]), "=r"(r[3]) : "r"(addr));
}

#define MBARRIER_INIT(a, n) \
    asm volatile("mbarrier.init.shared.b64 [%0], %1;" \
                 :: "r"((uint32_t)(a)), "r"((uint32_t)(n)) : "memory")
#define MBARRIER_EXPECT_TX(a, b) \
    asm volatile("mbarrier.arrive.expect_tx.shared.b64 _, [%0], %1;" \
                 :: "r"((uint32_t)(a)), "r"((uint32_t)(b)) : "memory")
#define MBARRIER_WAIT_PARITY(mbar, parity) do {                                   \
    uint32_t _m = (uint32_t)(mbar); uint32_t _p = (uint32_t)(parity);             \
    uint32_t _done;                                                               \
    asm volatile("{\n\t.reg .pred p;\n\t"                                         \
        "mbarrier.try_wait.parity.acquire.cta.shared::cta.b64 p, [%1], %2;\n\t"   \
        "selp.b32 %0, 1, 0, p;\n\t}" : "=r"(_done) : "r"(_m), "r"(_p) : "memory");\
    if (!_done) {                                                                 \
        asm volatile("{\n\t.reg .pred P1;\n\t"                                    \
        "WAIT_LOOP_%=:\n\t"                                                       \
        "mbarrier.try_wait.parity.acquire.cta.shared::cta.b64 P1, [%0], %1, 0x989680;\n\t" \
        "@P1 bra.uni WAIT_DONE_%=;\n\t"                                           \
        "bra.uni WAIT_LOOP_%=;\n\t"                                               \
        "WAIT_DONE_%=:\n\t}" :: "r"(_m), "r"(_p) : "memory");                     \
    }                                                                             \
} while (0)

__device__ __forceinline__ void bulk_g2s(uint32_t dst, const void* src,
                                         uint32_t bytes, uint32_t mbar) {
    asm volatile(
        "cp.async.bulk.shared::cluster.global.mbarrier::complete_tx::bytes "
        "[%0], [%1], %2, [%3];"
        :: "r"(dst), "l"(src), "r"(bytes), "r"(mbar) : "memory");
}

__device__ __forceinline__ void unrank_pair(int p, int& d, int& f) {
    int dd = 0;
    while (true) {
        int len = 33 - dd;
        if (p < len) { d = dd; f = dd + p; return; }
        p -= len; ++dd;
    }
}

// packed coef from (A, m, cAc) tables
__device__ __forceinline__ float coef_of(
    int p, const float (*A)[33], const float* m, float cac)
{
    if (p >= 561) return 0.f;
    int d, f; unrank_pair(p, d, f);
    if (f < 32)      return (d == f) ? A[d][d] : 2.f * A[d][f];
    else if (d < 32) return -2.f * m[d];
    else             return cac;
}

// ============================================================================
// Prep (one block per cluster): computes its own A_k/m_k/cAc_k AND cluster
// 0's (redundantly), writes centered fp16 B row + logcoef; block 0 also
// writes g_Cbar (cluster-0 fp32 coefs) and kmap.
// ============================================================================
__global__ void __launch_bounds__(128) prep_kernel(
    const float* __restrict__ centers,
    const float* __restrict__ S_all,
    const float* __restrict__ weights)
{
    __shared__ float sS[32][33];
    __shared__ float sS0[32][33];
    __shared__ float sA[32][33];
    __shared__ float sA0[32][33];
    __shared__ float sCen[64];          // [0:32) = cen_k, [32:64) = cen_0
    __shared__ float sM[32], sM0[32];
    __shared__ float sLogSumW, sCAC, sCAC0;

    const int k = blockIdx.x;
    const int tid = threadIdx.x;
    const float* Sg  = S_all + (size_t)k * 1024;

    for (int i = tid; i < 1024; i += 128) sS[i >> 5][i & 31] = Sg[i];
    for (int i = tid; i < 1024; i += 128) sS0[i >> 5][i & 31] = S_all[i];
    if (tid < 32) sCen[tid] = centers[k * 32 + tid];
    else if (tid < 64) sCen[tid] = centers[tid - 32];
    __syncthreads();

    if (tid < 32) {
        float s = 0.f;
        for (int j = tid; j < K_CL; j += 32) s += fabsf(weights[j]);
        #pragma unroll
        for (int o = 16; o; o >>= 1) s += __shfl_xor_sync(0xffffffffu, s, o);
        if (tid == 0) sLogSumW = logf(s + 1e-30f);
    }

    for (int i = tid; i < 1024; i += 128) {
        const int d = i >> 5, f = i & 31;
        float a = 0.f, a0 = 0.f;
        #pragma unroll
        for (int e = 0; e < 32; ++e) {
            a  = fmaf(sS[d][e],  sS[f][e],  a);
            a0 = fmaf(sS0[d][e], sS0[f][e], a0);
        }
        sA[d][f] = a;
        sA0[d][f] = a0;
    }
    __syncthreads();

    if (tid < 64) {
        const int d = tid & 31;
        const float (*A)[33] = (tid < 32) ? sA : sA0;
        const float* cen = (tid < 32) ? sCen : sCen + 32;
        float md = 0.f;
        #pragma unroll
        for (int f = 0; f < 32; ++f) md = fmaf(A[d][f], cen[f], md);
        if (tid < 32) sM[d] = md; else sM0[d] = md;
        float t = md * cen[d];
        #pragma unroll
        for (int o = 16; o; o >>= 1) t += __shfl_xor_sync(0xffffffffu, t, o);
        if (tid == 0) sCAC = t;
        if (tid == 32) sCAC0 = t;
    }
    __syncthreads();

    // centered fp16 B row (swizzled); block 0 writes zeros there and the
    // fp32 reference coefs + kmap.
    for (int p = tid; p < SEC; p += 128) {
        const float ck = coef_of(p, sA, sM, sCAC);
        const float c0 = coef_of(p, sA0, sM0, sCAC0);
        const __half ch = __float2half_rn(ck - c0);
        const int pc = p >> 6, kl = p & 63;
        const uint32_t raw = (uint32_t)(k * 128 + kl * 2);
        const uint32_t swz = raw ^ ((raw >> 3) & 0x70);
        *(__half*)((char*)g_B2 + (size_t)pc * 32768 + swz) = ch;
        if (k == 0) {
            g_Cbar[p] = c0;
            int d = 0, f = 0;
            if (p < 561) unrank_pair(p, d, f);
            g_kmap[p] = d | (f << 8);
        }
    }
    __syncthreads();

    // Cholesky of A_k (clobbers sA), warp 0
    if (tid < 32) {
        const int i = tid;
        for (int j = 0; j < 32; ++j) {
            float diag = sqrtf(sA[j][j]);
            __syncwarp();
            if (i == j) sA[j][j] = diag;
            else if (i > j) sA[i][j] = sA[i][j] / diag;
            __syncwarp();
            float lij = (i > j) ? sA[i][j] : 0.f;
            for (int c = j + 1; c <= i; ++c) sA[i][c] -= lij * sA[c][j];
            __syncwarp();
        }
        float ld = logf(sA[i][i]);
        #pragma unroll
        for (int o = 16; o; o >>= 1) ld += __shfl_xor_sync(0xffffffffu, ld, o);
        if (tid == 0)
            g_logcoef[k] = logf(fabsf(weights[k])) - sLogSumW + ld;
    }
}

// ============================================================================
// Main kernel
// ============================================================================
#define OFF_A    0u         // 2 buf x 16K = 32768
#define OFF_B    32768u     // 2 buf x 32K = 65536 -> 98304
#define OFF_X    98304u     // 128*33*4 = 16896 -> 115200
#define OFF_KM   115200u    // 576*4 -> 117504
#define OFF_LOG  117504u    // 256*4 -> 118528
#define OFF_CBAR 118528u    // 576*4 -> 120832
#define OFF_S    120832u    // 256*4 -> 121856
#define OFF_RED  121856u    // 128*4 float2 -> 125952
#define OFF_BAR  125952u
#define SMEM_END 125968u
#define SMEM_BYTES (SMEM_END + 1024u)

// build fp16 V image for one chunk (hi only)
__device__ __forceinline__ void build_a_tile(
    const float* __restrict__ px, const int* __restrict__ sKm,
    int pc, int h, char* aT, int p)
{
    const int pbase = pc * 64 + h * 32;
    const int rowbyte = p * 128;
    const int msk = (p & 7) << 4;
    #pragma unroll
    for (int g = 0; g < 4; ++g) {
        uint32_t wh[4];
        #pragma unroll
        for (int q = 0; q < 4; ++q) {
            unsigned short hs[2];
            #pragma unroll
            for (int e = 0; e < 2; ++e) {
                const int mp = sKm[pbase + g * 8 + q * 2 + e];
                const float v = px[mp & 255] * px[mp >> 8];
                hs[e] = __half_as_ushort(__float2half_rn(v));
            }
            wh[q] = (uint32_t)hs[0] | ((uint32_t)hs[1] << 16);
        }
        const int off = rowbyte + ((h * 64 + g * 16) ^ msk);
        *(uint4*)(aT + off) = make_uint4(wh[0], wh[1], wh[2], wh[3]);
    }
}

__device__ __forceinline__ void hmma_all(
    float (&acc)[4][8][4], const uint32_t (&a)[4][4], const uint32_t (&b)[4][4])
{
    #pragma unroll
    for (int mt = 0; mt < 4; ++mt)
        #pragma unroll
        for (int j = 0; j < 8; ++j) {
            const uint32_t b0 = b[j >> 1][(j & 1) * 2];
            const uint32_t b1 = b[j >> 1][(j & 1) * 2 + 1];
            asm volatile(
                "mma.sync.aligned.m16n8k16.row.col.f32.f16.f16.f32 "
                "{%0,%1,%2,%3}, {%4,%5,%6,%7}, {%8,%9}, {%0,%1,%2,%3};"
                : "+f"(acc[mt][j][0]), "+f"(acc[mt][j][1]),
                  "+f"(acc[mt][j][2]), "+f"(acc[mt][j][3])
                : "r"(a[mt][0]), "r"(a[mt][1]), "r"(a[mt][2]), "r"(a[mt][3]),
                  "r"(b0), "r"(b1));
        }
}

// single-pass chunk
__device__ __forceinline__ void mma_chunk(
    uint32_t aT, uint32_t bT, float (&acc)[4][8][4],
    int lane, int warpM, int warpN)
{
    const int rowA = (lane & 7) + ((lane >> 3) & 1) * 8;
    const int khA  = (lane >> 4) & 1;
    const int rowB = (lane & 7) + ((lane >> 4) & 1) * 8;
    const int khB  = (lane >> 3) & 1;
    const int sm   = (lane & 7) << 4;

    uint32_t aBase[4], bBase[4];
    #pragma unroll
    for (int mt = 0; mt < 4; ++mt)
        aBase[mt] = (uint32_t)((warpM * 64 + mt * 16 + rowA) * 128);
    #pragma unroll
    for (int nt = 0; nt < 4; ++nt)
        bBase[nt] = (uint32_t)((warpN * 64 + nt * 16 + rowB) * 128);

    #pragma unroll
    for (int ks = 0; ks < 4; ++ks) {
        const uint32_t colA = (uint32_t)((ks * 32 + khA * 16) ^ sm);
        const uint32_t colB = (uint32_t)((ks * 32 + khB * 16) ^ sm);
        uint32_t aH[4][4], bb[4][4];
        #pragma unroll
        for (int mt = 0; mt < 4; ++mt) ldsm_x4(aH[mt], aT + aBase[mt] + colA);
        #pragma unroll
        for (int nt = 0; nt < 4; ++nt) ldsm_x4(bb[nt], bT + bBase[nt] + colB);
        hmma_all(acc, aH, bb);
    }
}

__global__ void __launch_bounds__(TPB, 1)
gmm_mma_kernel(const float* __restrict__ points,
               const float* __restrict__ threshold,
               float* __restrict__ out)
{
    extern __shared__ char dsm[];
    const uint32_t rawb = smem_u32(dsm);
    const uint32_t base = (rawb + 1023u) & ~1023u;
    char* bp = dsm + (base - rawb);

    float* sX    = (float*)(bp + OFF_X);
    int*   sKm   = (int*)(bp + OFF_KM);
    float* sLog  = (float*)(bp + OFF_LOG);
    float* sCbar = (float*)(bp + OFF_CBAR);
    float* sS    = (float*)(bp + OFF_S);
    float2* sRed = (float2*)(bp + OFF_RED);

    const int tid = threadIdx.x;
    const int wid = tid >> 5;
    const int lane = tid & 31;
    const int gid = lane >> 2;
    const int tig = lane & 3;
    const int warpM = wid >> 2;
    const int warpN = wid & 3;
    const int p = tid & 127;
    const int h = tid >> 7;

    for (int i = tid; i < SEC; i += TPB) sKm[i] = g_kmap[i];
    for (int i = tid; i < SEC; i += TPB) sCbar[i] = g_Cbar[i];
    if (tid < K_CL) sLog[tid] = g_logcoef[tid];
    {
        const float4* src = (const float4*)(points +
            ((size_t)blockIdx.x * M_CTA + p) * 32 + h * 16);
        float* xr = sX + p * 33;
        #pragma unroll
        for (int r = 0; r < 4; ++r) {
            float4 v = src[r];
            xr[h * 16 + 4 * r] = v.x; xr[h * 16 + 4 * r + 1] = v.y;
            xr[h * 16 + 4 * r + 2] = v.z; xr[h * 16 + 4 * r + 3] = v.w;
        }
        if (h == 0) xr[32] = 1.0f;
    }

    const uint32_t bar[2] = { base + OFF_BAR, base + OFF_BAR + 8u };
    if (tid == 0) { MBARRIER_INIT(bar[0], 1); MBARRIER_INIT(bar[1], 1); }
    __syncthreads();

    const float* px = sX + p * 33;
    float acc[4][8][4];
    #pragma unroll
    for (int m = 0; m < 4; ++m)
        #pragma unroll
        for (int n = 0; n < 8; ++n)
            #pragma unroll
            for (int e = 0; e < 4; ++e) acc[m][n][e] = 0.f;

    // prologue: B chunk 0, A chunk 0, s_i (overlaps B0 flight)
    if (tid == 0) {
        MBARRIER_EXPECT_TX(bar[0], 32768u);
        bulk_g2s(base + OFF_B, (const char*)g_B2, 32768u, bar[0]);
    }
    build_a_tile(px, sKm, 0, h, bp + OFF_A, p);

    // s_i = x~^T A_0 x~ (exact fp32); this thread's half of the pairs
    {
        float part = 0.f;
        #pragma unroll 8
        for (int t = 0; t < 288; ++t) {
            const int pp = h * 288 + t;
            const int mp = sKm[pp];
            part = fmaf(sCbar[pp], px[mp & 255] * px[mp >> 8], part);
        }
        sS[tid] = part;
    }

    int phv[2] = { 0, 0 };
    for (int pc = 0; pc < NPC; ++pc) {
        const int buf = pc & 1, nb = buf ^ 1;
        MBARRIER_WAIT_PARITY(bar[buf], phv[buf]);
        phv[buf] ^= 1;
        __syncthreads();

        if (pc + 1 < NPC && tid == 0) {
            MBARRIER_EXPECT_TX(bar[nb], 32768u);
            bulk_g2s(base + OFF_B + (uint32_t)nb * 32768u,
                     (const char*)g_B2 + (size_t)(pc + 1) * 32768u,
                     32768u, bar[nb]);
        }

        mma_chunk(base + OFF_A + (uint32_t)buf * 16384u,
                  base + OFF_B + (uint32_t)buf * 32768u,
                  acc, lane, warpM, warpN);

        if (pc + 1 < NPC)
            build_a_tile(px, sKm, pc + 1, h,
                         bp + OFF_A + (uint32_t)nb * 16384u, p);
    }

    // ---- epilogue: weighted logsumexp, shifted by -0.5 s_i ----
    float lc[8][2];
    #pragma unroll
    for (int n = 0; n < 8; ++n) {
        lc[n][0] = sLog[warpN * 64 + n * 8 + tig * 2];
        lc[n][1] = sLog[warpN * 64 + n * 8 + tig * 2 + 1];
    }

    #pragma unroll
    for (int m = 0; m < 4; ++m) {
        #pragma unroll
        for (int rr = 0; rr < 2; ++rr) {
            float mx = -CUDART_INF_F, ss = 0.f;
            #pragma unroll
            for (int n = 0; n < 8; ++n) {
                #pragma unroll
                for (int e = 0; e < 2; ++e) {
                    const float v = fmaf(-0.5f, acc[m][n][rr * 2 + e], lc[n][e]);
                    const float nm = fmaxf(mx, v);
                    ss = ss * __expf(mx - nm) + __expf(v - nm);
                    mx = nm;
                }
            }
            #pragma unroll
            for (int off = 1; off <= 2; off <<= 1) {
                const float om = __shfl_xor_sync(0xffffffffu, mx, off);
                const float os = __shfl_xor_sync(0xffffffffu, ss, off);
                const float nm = fmaxf(mx, om);
                ss = ss * __expf(mx - nm) + os * __expf(om - nm);
                mx = nm;
            }
            if (tig == 0) {
                const int row = warpM * 64 + m * 16 + rr * 8 + gid;
                sRed[row * 4 + warpN] = make_float2(mx, ss);
            }
        }
    }
    __syncthreads();

    if (tid < M_CTA) {
        float2 v = sRed[tid * 4];
        float mx = v.x, ss = v.y;
        #pragma unroll
        for (int w = 1; w < 4; ++w) {
            const float2 o = sRed[tid * 4 + w];
            const float nm = fmaxf(mx, o.x);
            ss = ss * __expf(mx - nm) + o.y * __expf(o.x - nm);
            mx = nm;
        }
        const float s_i = sS[tid] + sS[tid + 128];
        out[(size_t)blockIdx.x * M_CTA + tid] =
            mx + logf(ss) - 0.5f * s_i - threshold[0];
    }
}

extern "C" void kernel_launch(void* const* d_in, const int* in_sizes, int n_in,
                              void* d_out, int out_size)
{
    const float* points  = (const float*)d_in[0];
    const float* centers = (const float*)d_in[1];
    const float* covs    = (const float*)d_in[2];
    const float* weights = (const float*)d_in[3];
    const float* thresh  = (const float*)d_in[4];
    float* out = (float*)d_out;

    cudaFuncSetAttribute(gmm_mma_kernel,
                         cudaFuncAttributeMaxDynamicSharedMemorySize, SMEM_BYTES);

    prep_kernel<<<K_CL, 128>>>(centers, covs, weights);
    gmm_mma_kernel<<<N_PTS / M_CTA, TPB, SMEM_BYTES>>>(points, thresh, out);
}